// round 2
// baseline (speedup 1.0000x reference)
#include <cuda_runtime.h>
#include <math.h>

// Problem constants (fixed shapes)
#define NS   4000   // sentences
#define SL   128    // sentence length
#define VEC  50     // word vec dim
#define PDIM 5      // pos emb dim
#define EMB  60     // VEC + 2*PDIM
#define HID  230
#define NBAG 500
#define NREL 25
#define LP   132    // padded smem row stride (floats)

// Intermediate sentence representations h = relu(max_l conv(emb) + b)  [NS, HID]
__device__ float g_h[NS * HID];

// ---- packed f32x2 helpers (FFMA2 — not emitted by ptxas from plain C++) ----
__device__ __forceinline__ unsigned long long pk2(float lo, float hi) {
    unsigned long long r;
    asm("mov.b64 %0, {%1, %2};" : "=l"(r) : "f"(lo), "f"(hi));
    return r;
}
__device__ __forceinline__ unsigned long long fma2(unsigned long long a,
                                                   unsigned long long b,
                                                   unsigned long long c) {
    unsigned long long d;
    asm("fma.rn.f32x2 %0, %1, %2, %3;" : "=l"(d) : "l"(a), "l"(b), "l"(c));
    return d;
}
__device__ __forceinline__ void unpk2(unsigned long long v, float& lo, float& hi) {
    asm("mov.b64 {%0, %1}, %2;" : "=f"(lo), "=f"(hi) : "l"(v));
}

// ---------------------------------------------------------------------------
// Kernel 1: fused embedding-gather + conv1d(k=3, SAME) + max-pool + relu
// One CTA per sentence, 256 threads (8 warps).
// Each lane computes 4 channels x 4 positions via packed f32x2 FMAs.
// Weights staged in smem PRE-DUPLICATED as (w,w) pairs -> LDS gives 64-bit
// FFMA2 operands directly.
// ---------------------------------------------------------------------------
__global__ void __launch_bounds__(256) enc_kernel(
    const int* __restrict__ X, const int* __restrict__ pos1,
    const int* __restrict__ pos2,
    const float* __restrict__ word_emb, const float* __restrict__ p1e,
    const float* __restrict__ p2e, const float* __restrict__ conv_w,
    const float* __restrict__ conv_b)
{
    extern __shared__ float sm[];
    float*  emb_s = sm;                        // [EMB][LP] = 7920 floats
    float2* w_s   = (float2*)(sm + EMB * LP);  // 8 warps * 720 float2 (dup pairs)
    int*    toks  = (int*)(w_s + 8 * 720);     // 3 * SL ints

    const int n   = blockIdx.x;
    const int tid = threadIdx.x;

    if (tid < SL) {
        toks[tid]          = X[n * SL + tid];
        toks[SL + tid]     = pos1[n * SL + tid];
        toks[2 * SL + tid] = pos2[n * SL + tid];
    }
    for (int e = tid; e < EMB; e += 256) {
        emb_s[e * LP + 0]   = 0.f;
        emb_s[e * LP + 129] = 0.f;
        emb_s[e * LP + 130] = 0.f;
        emb_s[e * LP + 131] = 0.f;
    }
    __syncthreads();

    // gather word part, transposed into [e][l+1]
    for (int idx = tid; idx < SL * VEC; idx += 256) {
        int l = idx / VEC, d = idx - l * VEC;
        emb_s[d * LP + l + 1] = word_emb[toks[l] * VEC + d];
    }
    // gather position parts
    for (int idx = tid; idx < SL * PDIM; idx += 256) {
        int l = idx / PDIM, d = idx - l * PDIM;
        emb_s[(VEC + d) * LP + l + 1]        = p1e[toks[SL + l] * PDIM + d];
        emb_s[(VEC + PDIM + d) * LP + l + 1] = p2e[toks[2 * SL + l] * PDIM + d];
    }
    __syncthreads();

    const int wid  = tid >> 5;
    const int lane = tid & 31;
    const int p0   = lane << 2;           // 4 contiguous output positions
    float2* wbuf   = w_s + wid * 720;

    for (int g = wid; g < 58; g += 8) {   // 58 channel-groups of 4
        const int c0 = g * 4;

        // stage weights as duplicated pairs: wbuf[e*12 + cl*3 + k] = (w, w)
        __syncwarp();
        for (int t = lane; t < 720; t += 32) {
            int cl = t / 180, r = t - cl * 180;
            int e = r / 3, k = r - e * 3;
            float v = (c0 + cl < HID) ? conv_w[(c0 + cl) * 180 + r] : 0.f;
            wbuf[e * 12 + cl * 3 + k] = make_float2(v, v);
        }
        __syncwarp();

        // acc[cl] as two packed pairs: positions (p0,p0+1) and (p0+2,p0+3)
        unsigned long long a01[4], a23[4];
        #pragma unroll
        for (int cl = 0; cl < 4; cl++) { a01[cl] = 0ull; a23[cl] = 0ull; }

        #pragma unroll 2
        for (int e = 0; e < EMB; e++) {
            const float4 xa = *reinterpret_cast<const float4*>(emb_s + e * LP + p0);
            const float2 xb = *reinterpret_cast<const float2*>(emb_s + e * LP + p0 + 4);
            // activation pairs (x_i, x_{i+1})
            unsigned long long x01 = pk2(xa.x, xa.y);
            unsigned long long x12 = pk2(xa.y, xa.z);
            unsigned long long x23 = pk2(xa.z, xa.w);
            unsigned long long x34 = pk2(xa.w, xb.x);
            unsigned long long x45 = pk2(xb.x, xb.y);
            // duplicated weight pairs: 12 x 64-bit loads (vectorized by compiler)
            const unsigned long long* wp =
                reinterpret_cast<const unsigned long long*>(wbuf + e * 12);
            #pragma unroll
            for (int cl = 0; cl < 4; cl++) {
                unsigned long long w0 = wp[cl * 3 + 0];
                unsigned long long w1 = wp[cl * 3 + 1];
                unsigned long long w2 = wp[cl * 3 + 2];
                a01[cl] = fma2(x01, w0, a01[cl]);
                a01[cl] = fma2(x12, w1, a01[cl]);
                a01[cl] = fma2(x23, w2, a01[cl]);
                a23[cl] = fma2(x23, w0, a23[cl]);
                a23[cl] = fma2(x34, w1, a23[cl]);
                a23[cl] = fma2(x45, w2, a23[cl]);
            }
        }

        // max over 4 local positions + warp butterfly, +bias, relu, store
        #pragma unroll
        for (int cl = 0; cl < 4; cl++) {
            float v0, v1, v2, v3;
            unpk2(a01[cl], v0, v1);
            unpk2(a23[cl], v2, v3);
            float m = fmaxf(fmaxf(v0, v1), fmaxf(v2, v3));
            #pragma unroll
            for (int o = 16; o > 0; o >>= 1)
                m = fmaxf(m, __shfl_xor_sync(0xffffffffu, m, o));
            if (lane == 0 && c0 + cl < HID) {
                float hv = m + conv_b[c0 + cl];
                g_h[n * HID + c0 + cl] = hv > 0.f ? hv : 0.f;
            }
        }
    }
}

// ---------------------------------------------------------------------------
// Kernel 2: per-bag softmax attention pooling + relation classifier
// ---------------------------------------------------------------------------
__global__ void __launch_bounds__(256) bag_kernel(
    const int* __restrict__ scope, const int* __restrict__ relation,
    const float* __restrict__ rel_w, const float* __restrict__ rel_b,
    float* __restrict__ out)
{
    __shared__ float rq[HID];
    __shared__ float rep[HID];
    __shared__ float logits[64];
    __shared__ float alpha[64];

    const int b    = blockIdx.x;
    const int tid  = threadIdx.x;
    const int wid  = tid >> 5;
    const int lane = tid & 31;

    const int s0 = scope[2 * b];
    const int s1 = scope[2 * b + 1];
    const int sz = s1 - s0;
    const int rel = relation[b];

    for (int d = tid; d < HID; d += 256) rq[d] = rel_w[rel * HID + d];
    __syncthreads();

    for (int i = wid; i < sz && i < 64; i += 8) {
        const float* hr = g_h + (s0 + i) * HID;
        float s = 0.f;
        for (int d = lane; d < HID; d += 32) s += hr[d] * rq[d];
        #pragma unroll
        for (int o = 16; o > 0; o >>= 1) s += __shfl_xor_sync(0xffffffffu, s, o);
        if (lane == 0) logits[i] = s;
    }
    __syncthreads();

    if (tid == 0) {
        float m = -1e30f;
        for (int i = 0; i < sz && i < 64; i++) m = fmaxf(m, logits[i]);
        float den = 0.f;
        for (int i = 0; i < sz && i < 64; i++) {
            float e = expf(logits[i] - m);
            alpha[i] = e;
            den += e;
        }
        float inv = 1.f / den;
        for (int i = 0; i < sz && i < 64; i++) alpha[i] *= inv;
    }
    __syncthreads();

    for (int d = tid; d < HID; d += 256) {
        float a = 0.f;
        for (int i = 0; i < sz && i < 64; i++)
            a += alpha[i] * g_h[(s0 + i) * HID + d];
        rep[d] = a;
    }
    __syncthreads();

    for (int r = wid; r < NREL; r += 8) {
        float s = 0.f;
        for (int d = lane; d < HID; d += 32) s += rep[d] * rel_w[r * HID + d];
        #pragma unroll
        for (int o = 16; o > 0; o >>= 1) s += __shfl_xor_sync(0xffffffffu, s, o);
        if (lane == 0) out[b * NREL + r] = s + rel_b[r];
    }
}

// ---------------------------------------------------------------------------
extern "C" void kernel_launch(void* const* d_in, const int* in_sizes, int n_in,
                              void* d_out, int out_size)
{
    const int*   X        = (const int*)d_in[0];
    const int*   pos1     = (const int*)d_in[1];
    const int*   pos2     = (const int*)d_in[2];
    const int*   scope    = (const int*)d_in[5];
    const int*   relation = (const int*)d_in[6];
    const float* word_emb = (const float*)d_in[7];
    const float* p1e      = (const float*)d_in[8];
    const float* p2e      = (const float*)d_in[9];
    const float* conv_w   = (const float*)d_in[10];
    const float* conv_b   = (const float*)d_in[11];
    const float* rel_w    = (const float*)d_in[12];
    const float* rel_b    = (const float*)d_in[13];
    float*       out      = (float*)d_out;

    const int smem_bytes = EMB * LP * (int)sizeof(float)     // emb tile
                         + 8 * 720 * (int)sizeof(float2)     // dup weight pairs
                         + 3 * SL * (int)sizeof(int);        // tokens
    cudaFuncSetAttribute(enc_kernel,
                         cudaFuncAttributeMaxDynamicSharedMemorySize, smem_bytes);

    enc_kernel<<<NS, 256, smem_bytes>>>(X, pos1, pos2, word_emb, p1e, p2e,
                                        conv_w, conv_b);
    bag_kernel<<<NBAG, 256>>>(scope, relation, rel_w, rel_b, out);
}

// round 5
// speedup vs baseline: 1.5310x; 1.5310x over previous
#include <cuda_runtime.h>
#include <math.h>
#include <stdint.h>

// Problem constants (fixed shapes)
#define NS   4000   // sentences
#define SL   128    // sentence length
#define VEC  50     // word vec dim
#define PDIM 5      // pos emb dim
#define EMB  60     // VEC + 2*PDIM
#define HID  230
#define NBAG 500
#define NREL 25
#define LP   132    // padded smem row stride (floats)
#define NGRP 29     // 29 groups x 8 channels = 232 >= HID

// Intermediate sentence representations h = relu(max_l conv(emb) + b)  [NS, HID]
__device__ float g_h[NS * HID];

typedef unsigned long long ull;

// ---- packed f32x2 helpers ----
__device__ __forceinline__ ull pk2(float lo, float hi) {
    ull r;
    asm("mov.b64 %0, {%1, %2};" : "=l"(r) : "f"(lo), "f"(hi));
    return r;
}
__device__ __forceinline__ ull fma2(ull a, ull b, ull c) {
    ull d;
    asm("fma.rn.f32x2 %0, %1, %2, %3;" : "=l"(d) : "l"(a), "l"(b), "l"(c));
    return d;
}
__device__ __forceinline__ void unpk2(ull v, float& lo, float& hi) {
    asm("mov.b64 {%0, %1}, %2;" : "=f"(lo), "=f"(hi) : "l"(v));
}

// ---------------------------------------------------------------------------
// Kernel 1: fused embedding-gather + conv1d(k=3, SAME) + max-pool + relu
// One CTA per sentence, 256 threads (8 warps).
// FFMA2 with CHANNEL-paired accumulators:
//   acc(pos j, pair cp) covers channels (c0+2cp, c0+2cp+1).
//   Weights staged in smem as adjacent-channel float2 -> one broadcast LDS.64
//   per pair (no duplication). Activations duplicated via 6 pk2/e (alu pipe).
// Each warp: 8 channels x 4 positions -> 48 FFMA2 per e (96 MACs).
// ---------------------------------------------------------------------------
__global__ void __launch_bounds__(256) enc_kernel(
    const int* __restrict__ X, const int* __restrict__ pos1,
    const int* __restrict__ pos2,
    const float* __restrict__ word_emb, const float* __restrict__ p1e,
    const float* __restrict__ p2e, const float* __restrict__ conv_w,
    const float* __restrict__ conv_b)
{
    extern __shared__ float sm[];
    float*  emb_s = sm;                        // [EMB][LP] = 7920 floats
    float2* w_s   = (float2*)(sm + EMB * LP);  // 8 warps * 720 float2 pairs
    int*    toks  = (int*)(w_s + 8 * 720);     // 3 * SL ints

    const int n   = blockIdx.x;
    const int tid = threadIdx.x;

    if (tid < SL) {
        toks[tid]          = X[n * SL + tid];
        toks[SL + tid]     = pos1[n * SL + tid];
        toks[2 * SL + tid] = pos2[n * SL + tid];
    }
    for (int e = tid; e < EMB; e += 256) {
        emb_s[e * LP + 0]   = 0.f;
        emb_s[e * LP + 129] = 0.f;
        emb_s[e * LP + 130] = 0.f;
        emb_s[e * LP + 131] = 0.f;
    }
    __syncthreads();

    // gather word part, transposed into [e][l+1]
    for (int idx = tid; idx < SL * VEC; idx += 256) {
        int l = idx / VEC, d = idx - l * VEC;
        emb_s[d * LP + l + 1] = word_emb[toks[l] * VEC + d];
    }
    // gather position parts
    for (int idx = tid; idx < SL * PDIM; idx += 256) {
        int l = idx / PDIM, d = idx - l * PDIM;
        emb_s[(VEC + d) * LP + l + 1]        = p1e[toks[SL + l] * PDIM + d];
        emb_s[(VEC + PDIM + d) * LP + l + 1] = p2e[toks[2 * SL + l] * PDIM + d];
    }
    __syncthreads();

    const int wid  = tid >> 5;
    const int lane = tid & 31;
    const int p0   = lane << 2;            // 4 contiguous output positions
    float2* wbuf   = w_s + wid * 720;      // this warp's staged pairs

    for (int g = wid; g < NGRP; g += 8) {  // 29 groups of 8 channels
        const int c0 = g * 8;

        // stage weights as channel pairs: wbuf[e*12 + k*4 + cp] =
        //   ( w[c0+2cp][e][k], w[c0+2cp+1][e][k] )
        __syncwarp();
        for (int t = lane; t < 720; t += 32) {
            int e = t / 12, r = t - e * 12;
            int k = r >> 2, cp = r & 3;
            int c = c0 + 2 * cp;
            float a = (c     < HID) ? conv_w[c * 180 + e * 3 + k]       : 0.f;
            float b = (c + 1 < HID) ? conv_w[(c + 1) * 180 + e * 3 + k] : 0.f;
            wbuf[t] = make_float2(a, b);
        }
        __syncwarp();

        // acc[pos j][pair cp]
        ull acc[4][4];
        #pragma unroll
        for (int j = 0; j < 4; j++)
            #pragma unroll
            for (int cp = 0; cp < 4; cp++) acc[j][cp] = 0ull;

        #pragma unroll 2
        for (int e = 0; e < EMB; e++) {
            const float4 xa = *reinterpret_cast<const float4*>(emb_s + e * LP + p0);
            const float2 xb = *reinterpret_cast<const float2*>(emb_s + e * LP + p0 + 4);
            ull Xd[6];
            Xd[0] = pk2(xa.x, xa.x);
            Xd[1] = pk2(xa.y, xa.y);
            Xd[2] = pk2(xa.z, xa.z);
            Xd[3] = pk2(xa.w, xa.w);
            Xd[4] = pk2(xb.x, xb.x);
            Xd[5] = pk2(xb.y, xb.y);
            const ull* wp = reinterpret_cast<const ull*>(wbuf + e * 12);
            #pragma unroll
            for (int k = 0; k < 3; k++) {
                ull w0 = wp[k * 4 + 0];
                ull w1 = wp[k * 4 + 1];
                ull w2 = wp[k * 4 + 2];
                ull w3 = wp[k * 4 + 3];
                #pragma unroll
                for (int j = 0; j < 4; j++) {
                    acc[j][0] = fma2(Xd[j + k], w0, acc[j][0]);
                    acc[j][1] = fma2(Xd[j + k], w1, acc[j][1]);
                    acc[j][2] = fma2(Xd[j + k], w2, acc[j][2]);
                    acc[j][3] = fma2(Xd[j + k], w3, acc[j][3]);
                }
            }
        }

        // epilogue: per pair, max over 4 local positions + warp butterfly
        #pragma unroll
        for (int cp = 0; cp < 4; cp++) {
            float a0, b0, a1, b1, a2, b2, a3, b3;
            unpk2(acc[0][cp], a0, b0);
            unpk2(acc[1][cp], a1, b1);
            unpk2(acc[2][cp], a2, b2);
            unpk2(acc[3][cp], a3, b3);
            float mlo = fmaxf(fmaxf(a0, a1), fmaxf(a2, a3));
            float mhi = fmaxf(fmaxf(b0, b1), fmaxf(b2, b3));
            #pragma unroll
            for (int o = 16; o > 0; o >>= 1) {
                mlo = fmaxf(mlo, __shfl_xor_sync(0xffffffffu, mlo, o));
                mhi = fmaxf(mhi, __shfl_xor_sync(0xffffffffu, mhi, o));
            }
            if (lane == 0) {
                int c = c0 + 2 * cp;
                if (c < HID) {
                    float hv = mlo + conv_b[c];
                    g_h[n * HID + c] = hv > 0.f ? hv : 0.f;
                }
                if (c + 1 < HID) {
                    float hv = mhi + conv_b[c + 1];
                    g_h[n * HID + c + 1] = hv > 0.f ? hv : 0.f;
                }
            }
        }
    }
}

// ---------------------------------------------------------------------------
// Kernel 2: per-bag softmax attention pooling + relation classifier
// ---------------------------------------------------------------------------
__global__ void __launch_bounds__(256) bag_kernel(
    const int* __restrict__ scope, const int* __restrict__ relation,
    const float* __restrict__ rel_w, const float* __restrict__ rel_b,
    float* __restrict__ out)
{
    __shared__ float rq[HID];
    __shared__ float rep[HID];
    __shared__ float logits[64];
    __shared__ float alpha[64];

    const int b = blockIdx.x, tid = threadIdx.x;
    const int wid = tid >> 5, lane = tid & 31;
    const int s0 = scope[2 * b], s1 = scope[2 * b + 1];
    const int sz = s1 - s0;
    const int rel = relation[b];

    for (int d = tid; d < HID; d += 256) rq[d] = rel_w[rel * HID + d];
    __syncthreads();

    for (int i = wid; i < sz && i < 64; i += 8) {
        const float* hr = g_h + (s0 + i) * HID;
        float s = 0.f;
        for (int d = lane; d < HID; d += 32) s += hr[d] * rq[d];
        #pragma unroll
        for (int o = 16; o > 0; o >>= 1) s += __shfl_xor_sync(0xffffffffu, s, o);
        if (lane == 0) logits[i] = s;
    }
    __syncthreads();

    if (tid == 0) {
        float m = -1e30f;
        for (int i = 0; i < sz && i < 64; i++) m = fmaxf(m, logits[i]);
        float den = 0.f;
        for (int i = 0; i < sz && i < 64; i++) {
            float e = expf(logits[i] - m);
            alpha[i] = e; den += e;
        }
        float inv = 1.f / den;
        for (int i = 0; i < sz && i < 64; i++) alpha[i] *= inv;
    }
    __syncthreads();

    for (int d = tid; d < HID; d += 256) {
        float a = 0.f;
        for (int i = 0; i < sz && i < 64; i++)
            a += alpha[i] * g_h[(s0 + i) * HID + d];
        rep[d] = a;
    }
    __syncthreads();

    for (int r = wid; r < NREL; r += 8) {
        float s = 0.f;
        for (int d = lane; d < HID; d += 32) s += rep[d] * rel_w[r * HID + d];
        #pragma unroll
        for (int o = 16; o > 0; o >>= 1) s += __shfl_xor_sync(0xffffffffu, s, o);
        if (lane == 0) out[b * NREL + r] = s + rel_b[r];
    }
}

// ---------------------------------------------------------------------------
extern "C" void kernel_launch(void* const* d_in, const int* in_sizes, int n_in,
                              void* d_out, int out_size)
{
    const int*   X        = (const int*)d_in[0];
    const int*   pos1     = (const int*)d_in[1];
    const int*   pos2     = (const int*)d_in[2];
    const int*   scope    = (const int*)d_in[5];
    const int*   relation = (const int*)d_in[6];
    const float* word_emb = (const float*)d_in[7];
    const float* p1e      = (const float*)d_in[8];
    const float* p2e      = (const float*)d_in[9];
    const float* conv_w   = (const float*)d_in[10];
    const float* conv_b   = (const float*)d_in[11];
    const float* rel_w    = (const float*)d_in[12];
    const float* rel_b    = (const float*)d_in[13];
    float*       out      = (float*)d_out;

    const int smem_bytes = EMB * LP * (int)sizeof(float)     // emb tile (31680)
                         + 8 * 720 * (int)sizeof(float2)     // weight pairs (46080)
                         + 3 * SL * (int)sizeof(int);        // tokens (1536)
    cudaFuncSetAttribute(enc_kernel,
                         cudaFuncAttributeMaxDynamicSharedMemorySize, smem_bytes);

    enc_kernel<<<NS, 256, smem_bytes>>>(X, pos1, pos2, word_emb, p1e, p2e,
                                        conv_w, conv_b);
    bag_kernel<<<NBAG, 256>>>(scope, relation, rel_w, rel_b, out);
}

// round 6
// speedup vs baseline: 1.6623x; 1.0857x over previous
#include <cuda_runtime.h>
#include <cuda_bf16.h>
#include <math.h>
#include <stdint.h>

// ---------------- problem constants ----------------
#define NS   4000
#define SL   128
#define VEC  50
#define PDIM 5
#define EMB  60
#define HID  230
#define NBAG 500
#define NREL 25

#define NPC  232          // channels padded to 29*8
#define KT   192          // K = 3 taps * 64 (EMB padded to 64)
#define GRID_ENC 152

// smem offsets from 128-aligned base
#define OFF_BH   0u                    // 232*384 = 89088
#define OFF_BL   89088u                // 89088
#define OFF_A    178176u               // 128*384 = 49152 (scratch aliases here)
#define OFF_TOKS 227328u               // 3*128*4 = 1536 -> end 228864
#define SMEM_NEED (228864 + 128)

__device__ float g_h[NS * HID];
__device__ __nv_bfloat16 g_Bh[NPC * KT];
__device__ __nv_bfloat16 g_Bl[NPC * KT];

// ---------------- helpers ----------------
__device__ __forceinline__ uint32_t smem_u32(const void* p) {
    uint32_t a;
    asm("{ .reg .u64 t; cvta.to.shared.u64 t, %1; cvt.u32.u64 %0, t; }"
        : "=r"(a) : "l"(p));
    return a;
}
__device__ __forceinline__ void sts16(uint32_t a, unsigned short v) {
    asm volatile("st.shared.u16 [%0], %1;" :: "r"(a), "h"(v));
}
__device__ __forceinline__ void sts64(uint32_t a, uint2 v) {
    asm volatile("st.shared.v2.u32 [%0], {%1,%2};" :: "r"(a), "r"(v.x), "r"(v.y));
}
__device__ __forceinline__ void sts128z(uint32_t a) {
    asm volatile("st.shared.v4.u32 [%0], {%1,%1,%1,%1};" :: "r"(a), "r"(0u));
}
__device__ __forceinline__ void ldsm4(uint32_t& r0, uint32_t& r1, uint32_t& r2,
                                      uint32_t& r3, uint32_t addr) {
    asm volatile("ldmatrix.sync.aligned.m8n8.x4.shared.b16 {%0,%1,%2,%3}, [%4];"
                 : "=r"(r0), "=r"(r1), "=r"(r2), "=r"(r3) : "r"(addr));
}
__device__ __forceinline__ void ldsm2(uint32_t& r0, uint32_t& r1, uint32_t addr) {
    asm volatile("ldmatrix.sync.aligned.m8n8.x2.shared.b16 {%0,%1}, [%2];"
                 : "=r"(r0), "=r"(r1) : "r"(addr));
}
__device__ __forceinline__ void mma16816(float* c, uint32_t a0, uint32_t a1,
                                         uint32_t a2, uint32_t a3,
                                         uint32_t b0, uint32_t b1) {
    asm volatile(
        "mma.sync.aligned.m16n8k16.row.col.f32.bf16.bf16.f32 "
        "{%0,%1,%2,%3}, {%4,%5,%6,%7}, {%8,%9}, {%0,%1,%2,%3};"
        : "+f"(c[0]), "+f"(c[1]), "+f"(c[2]), "+f"(c[3])
        : "r"(a0), "r"(a1), "r"(a2), "r"(a3), "r"(b0), "r"(b1));
}

// ---------------- kernel 0: conv_w -> bf16 hi/lo, [ch][k] im2col layout ----
__global__ void prepB(const float* __restrict__ conv_w) {
    int idx = blockIdx.x * blockDim.x + threadIdx.x;
    if (idx >= NPC * KT) return;
    int c = idx / KT, k = idx - c * KT;
    int tap = k >> 6, e = k & 63;
    float v = 0.f;
    if (c < HID && e < EMB) v = conv_w[(c * EMB + e) * 3 + tap];
    __nv_bfloat16 h = __float2bfloat16(v);
    __nv_bfloat16 l = __float2bfloat16(v - __bfloat162float(h));
    g_Bh[idx] = h;
    g_Bl[idx] = l;
}

// ---------------- kernel 1: persistent mma.sync encoder ----------------
// D[pos 128, ch 232] = A[pos, K=192] * B^T ; K = 3 taps x 64 (im2col, SAME).
// 3-term bf16 split: Ah*Bh + Ah*Bl + Al*Bh, fp32 register accumulators.
// Warp w: m-rows [32*(w&3), +32) (2 m16 tiles), n-tiles [15*(w>>2), +15/14).
// XOR swizzle (bits 4-6 by row%8) for conflict-free ldmatrix.
__global__ void __launch_bounds__(256, 1) enc_kernel(
    const int* __restrict__ X, const int* __restrict__ pos1,
    const int* __restrict__ pos2,
    const float* __restrict__ word_emb, const float* __restrict__ p1e,
    const float* __restrict__ p2e, const float* __restrict__ conv_b)
{
    extern __shared__ char sm_raw[];
    const uint32_t raw  = smem_u32(sm_raw);
    const uint32_t base = (raw + 127u) & ~127u;
    char* bp   = sm_raw + (base - raw);
    int*  toks = (int*)(bp + OFF_TOKS);
    float* scr = (float*)(bp + OFF_A);      // epilogue scratch aliases A

    const int tid  = threadIdx.x;
    const int wid  = tid >> 5;
    const int lane = tid & 31;

    // ---- stage resident weights (hi+lo), swizzled [n][k] rows of 384B
    for (int t = tid; t < NPC * KT / 4; t += 256) {
        int idx = t * 4;
        int c = idx / KT, k = idx - c * KT;
        uint32_t off = (uint32_t)c * 384u
                     + (((uint32_t)k * 2u) ^ (((uint32_t)(c & 7)) << 4));
        sts64(base + OFF_BH + off, *reinterpret_cast<const uint2*>(g_Bh + idx));
        sts64(base + OFF_BL + off, *reinterpret_cast<const uint2*>(g_Bl + idx));
    }
    __syncthreads();

    // ---- per-warp tiling constants
    const int mq  = wid & 3;             // m-block: rows [32*mq, 32*mq+32)
    const int nh  = wid >> 2;            // n-half
    const int ntn = nh ? 14 : 15;        // tiles in this half
    const int nt0 = nh * 15;             // first n-tile index

    const int arow     = mq * 32 + (lane & 7) + ((lane >> 3) & 1) * 8;
    const uint32_t akb0 = ((uint32_t)(lane >> 4) & 1u) * 16u;
    const uint32_t asw  = ((uint32_t)(lane & 7)) << 4;
    const uint32_t abase0 = base + OFF_A + (uint32_t)arow * 384u;
    const uint32_t abase1 = abase0 + 16u * 384u;

    const uint32_t bkb0   = ((uint32_t)(lane >> 3) & 1u) * 16u;
    const uint32_t bsw    = ((uint32_t)(lane & 7)) << 4;
    const uint32_t brow   = ((uint32_t)(lane & 7)) * 384u;

    for (int n = blockIdx.x; n < NS; n += GRID_ENC) {
        // ---- stage token ids
        for (int t = tid; t < 3 * SL; t += 256) {
            int which = t >> 7, l = t & 127;
            const int* src = (which == 0) ? X : (which == 1 ? pos1 : pos2);
            toks[t] = src[n * SL + l];
        }

        float acc[2][15][4];
        #pragma unroll
        for (int mt = 0; mt < 2; mt++)
            #pragma unroll
            for (int nt = 0; nt < 15; nt++)
                #pragma unroll
                for (int q = 0; q < 4; q++) acc[mt][nt][q] = 0.f;

        for (int pass = 0; pass < 2; pass++) {
            // zero A tile (covers K-pad + SAME-pad slots)
            for (int t = tid; t < 3072; t += 256)
                sts128z(base + OFF_A + (uint32_t)t * 16u);
            __syncthreads();

            // gather + bf16 (hi or lo) + scatter to 3 tap slabs, swizzled
            for (int idx = tid; idx < SL * EMB; idx += 256) {
                int l = idx / EMB, e = idx - l * EMB;
                float x;
                if (e < VEC)             x = word_emb[toks[l] * VEC + e];
                else if (e < VEC + PDIM) x = p1e[toks[SL + l] * PDIM + (e - VEC)];
                else                     x = p2e[toks[2 * SL + l] * PDIM + (e - VEC - PDIM)];
                __nv_bfloat16 hv = __float2bfloat16(x);
                __nv_bfloat16 v  = pass ? __float2bfloat16(x - __bfloat162float(hv)) : hv;
                unsigned short u = __bfloat16_as_ushort(v);
                #pragma unroll
                for (int tap = 0; tap < 3; tap++) {
                    int row = l + 1 - tap;
                    if ((unsigned)row < 128u) {
                        uint32_t kb  = (uint32_t)(tap * 64 + e) * 2u;
                        uint32_t off = (uint32_t)row * 384u
                                     + (kb ^ (((uint32_t)(row & 7)) << 4));
                        sts16(base + OFF_A + off, u);
                    }
                }
            }
            __syncthreads();

            // mma: pass0 -> Ah*(Bh + Bl); pass1 -> Al*Bh
            #pragma unroll 2
            for (int ks = 0; ks < 12; ks++) {
                uint32_t ak = (((uint32_t)ks * 32u) + akb0) ^ asw;
                uint32_t a0, a1, a2, a3, a4, a5, a6, a7;
                ldsm4(a0, a1, a2, a3, abase0 + ak);
                ldsm4(a4, a5, a6, a7, abase1 + ak);
                uint32_t bk = (((uint32_t)ks * 32u) + bkb0) ^ bsw;
                #pragma unroll
                for (int nt = 0; nt < 15; nt++) {
                    if (nt < ntn) {
                        uint32_t baddr = base + OFF_BH
                                       + (uint32_t)(nt0 + nt) * 3072u + brow + bk;
                        uint32_t b0, b1;
                        ldsm2(b0, b1, baddr);
                        mma16816(acc[0][nt], a0, a1, a2, a3, b0, b1);
                        mma16816(acc[1][nt], a4, a5, a6, a7, b0, b1);
                        if (pass == 0) {
                            uint32_t c0, c1;
                            ldsm2(c0, c1, baddr + (OFF_BL - OFF_BH));
                            mma16816(acc[0][nt], a0, a1, a2, a3, c0, c1);
                            mma16816(acc[1][nt], a4, a5, a6, a7, c0, c1);
                        }
                    }
                }
            }
            __syncthreads();   // A reads done before rebuild / epilogue reuse
        }

        // ---- epilogue: max over positions, cross-warp via scratch
        // lane j holds cols 2*(j%4), 2*(j%4)+1; rows j/4, j/4+8 per m16 tile
        #pragma unroll
        for (int nt = 0; nt < 15; nt++) {
            if (nt < ntn) {
                float ve = fmaxf(fmaxf(acc[0][nt][0], acc[0][nt][2]),
                                 fmaxf(acc[1][nt][0], acc[1][nt][2]));
                float vo = fmaxf(fmaxf(acc[0][nt][1], acc[0][nt][3]),
                                 fmaxf(acc[1][nt][1], acc[1][nt][3]));
                #pragma unroll
                for (int o = 4; o <= 16; o <<= 1) {
                    ve = fmaxf(ve, __shfl_xor_sync(0xffffffffu, ve, o));
                    vo = fmaxf(vo, __shfl_xor_sync(0xffffffffu, vo, o));
                }
                if (lane < 4) {
                    int col = (nt0 + nt) * 8 + 2 * lane;
                    scr[mq * NPC + col]     = ve;
                    scr[mq * NPC + col + 1] = vo;
                }
            }
        }
        __syncthreads();
        if (tid < HID) {
            float m = fmaxf(fmaxf(scr[tid], scr[NPC + tid]),
                            fmaxf(scr[2 * NPC + tid], scr[3 * NPC + tid]));
            float hv = m + conv_b[tid];
            g_h[n * HID + tid] = hv > 0.f ? hv : 0.f;
        }
        __syncthreads();   // scratch/toks reused next sentence
    }
}

// ---------------- kernel 2: bag attention + classifier ----------------
__global__ void __launch_bounds__(256) bag_kernel(
    const int* __restrict__ scope, const int* __restrict__ relation,
    const float* __restrict__ rel_w, const float* __restrict__ rel_b,
    float* __restrict__ out)
{
    __shared__ float rq[HID];
    __shared__ float rep[HID];
    __shared__ float logits[64];
    __shared__ float alpha[64];

    const int b = blockIdx.x, tid = threadIdx.x;
    const int wid = tid >> 5, lane = tid & 31;
    const int s0 = scope[2 * b], s1 = scope[2 * b + 1];
    const int sz = s1 - s0;
    const int rel = relation[b];

    for (int d = tid; d < HID; d += 256) rq[d] = rel_w[rel * HID + d];
    __syncthreads();

    for (int i = wid; i < sz && i < 64; i += 8) {
        const float* hr = g_h + (s0 + i) * HID;
        float s = 0.f;
        for (int d = lane; d < HID; d += 32) s += hr[d] * rq[d];
        #pragma unroll
        for (int o = 16; o > 0; o >>= 1) s += __shfl_xor_sync(0xffffffffu, s, o);
        if (lane == 0) logits[i] = s;
    }
    __syncthreads();

    if (tid == 0) {
        float m = -1e30f;
        for (int i = 0; i < sz && i < 64; i++) m = fmaxf(m, logits[i]);
        float den = 0.f;
        for (int i = 0; i < sz && i < 64; i++) {
            float e = expf(logits[i] - m);
            alpha[i] = e; den += e;
        }
        float inv = 1.f / den;
        for (int i = 0; i < sz && i < 64; i++) alpha[i] *= inv;
    }
    __syncthreads();

    for (int d = tid; d < HID; d += 256) {
        float a = 0.f;
        for (int i = 0; i < sz && i < 64; i++)
            a += alpha[i] * g_h[(s0 + i) * HID + d];
        rep[d] = a;
    }
    __syncthreads();

    for (int r = wid; r < NREL; r += 8) {
        float s = 0.f;
        for (int d = lane; d < HID; d += 32) s += rep[d] * rel_w[r * HID + d];
        #pragma unroll
        for (int o = 16; o > 0; o >>= 1) s += __shfl_xor_sync(0xffffffffu, s, o);
        if (lane == 0) out[b * NREL + r] = s + rel_b[r];
    }
}

// ---------------------------------------------------------------------------
extern "C" void kernel_launch(void* const* d_in, const int* in_sizes, int n_in,
                              void* d_out, int out_size)
{
    const int*   X        = (const int*)d_in[0];
    const int*   pos1     = (const int*)d_in[1];
    const int*   pos2     = (const int*)d_in[2];
    const int*   scope    = (const int*)d_in[5];
    const int*   relation = (const int*)d_in[6];
    const float* word_emb = (const float*)d_in[7];
    const float* p1e      = (const float*)d_in[8];
    const float* p2e      = (const float*)d_in[9];
    const float* conv_w   = (const float*)d_in[10];
    const float* conv_b   = (const float*)d_in[11];
    const float* rel_w    = (const float*)d_in[12];
    const float* rel_b    = (const float*)d_in[13];
    float*       out      = (float*)d_out;

    cudaFuncSetAttribute(enc_kernel,
                         cudaFuncAttributeMaxDynamicSharedMemorySize, SMEM_NEED);

    prepB<<<(NPC * KT + 255) / 256, 256>>>(conv_w);
    enc_kernel<<<GRID_ENC, 256, SMEM_NEED>>>(X, pos1, pos2, word_emb, p1e, p2e,
                                             conv_b);
    bag_kernel<<<NBAG, 256>>>(scope, relation, rel_w, rel_b, out);
}

// round 7
// speedup vs baseline: 2.6687x; 1.6054x over previous
#include <cuda_runtime.h>
#include <cuda_bf16.h>
#include <math.h>
#include <stdint.h>

// ---------------- problem constants ----------------
#define NS   4000
#define SL   128
#define VEC  50
#define PDIM 5
#define EMB  60
#define HID  230
#define NBAG 500
#define NREL 25

#define NPC2 240          // channels padded to 30 n-tiles (ldsm4 pairs)
#define KT   192          // K = 3 taps * 64
#define GRID_ENC 152

// smem offsets (base 128-aligned)
#define OFF_BH   0u             // 240*384 = 92160
#define OFF_BL   92160u         // 92160
#define OFF_AH   184320u        // 130 rows * 128B = 16640
#define OFF_AL   200960u        // 16640
#define OFF_SCR  217600u        // 2*240*4 = 1920
#define SMEM_NEED (219520 + 128)

__device__ float g_h[NS * HID];
__device__ __nv_bfloat16 g_Bh[NPC2 * KT];
__device__ __nv_bfloat16 g_Bl[NPC2 * KT];

// ---------------- helpers ----------------
__device__ __forceinline__ uint32_t smem_u32(const void* p) {
    uint32_t a;
    asm("{ .reg .u64 t; cvta.to.shared.u64 t, %1; cvt.u32.u64 %0, t; }"
        : "=r"(a) : "l"(p));
    return a;
}
__device__ __forceinline__ void sts32(uint32_t a, uint32_t v) {
    asm volatile("st.shared.u32 [%0], %1;" :: "r"(a), "r"(v));
}
__device__ __forceinline__ void sts64(uint32_t a, uint2 v) {
    asm volatile("st.shared.v2.u32 [%0], {%1,%2};" :: "r"(a), "r"(v.x), "r"(v.y));
}
__device__ __forceinline__ void sts128z(uint32_t a) {
    asm volatile("st.shared.v4.u32 [%0], {%1,%1,%1,%1};" :: "r"(a), "r"(0u));
}
__device__ __forceinline__ void ldsm4(uint32_t& r0, uint32_t& r1, uint32_t& r2,
                                      uint32_t& r3, uint32_t addr) {
    asm volatile("ldmatrix.sync.aligned.m8n8.x4.shared.b16 {%0,%1,%2,%3}, [%4];"
                 : "=r"(r0), "=r"(r1), "=r"(r2), "=r"(r3) : "r"(addr));
}
__device__ __forceinline__ void mma16816(float* c, const uint32_t* a,
                                         uint32_t b0, uint32_t b1) {
    asm volatile(
        "mma.sync.aligned.m16n8k16.row.col.f32.bf16.bf16.f32 "
        "{%0,%1,%2,%3}, {%4,%5,%6,%7}, {%8,%9}, {%0,%1,%2,%3};"
        : "+f"(c[0]), "+f"(c[1]), "+f"(c[2]), "+f"(c[3])
        : "r"(a[0]), "r"(a[1]), "r"(a[2]), "r"(a[3]), "r"(b0), "r"(b1));
}

// ---------------- kernel 0: conv_w -> bf16 hi/lo im2col [c][tap*64+e] -------
__global__ void prepB(const float* __restrict__ conv_w) {
    int idx = blockIdx.x * blockDim.x + threadIdx.x;
    if (idx >= NPC2 * KT) return;
    int c = idx / KT, k = idx - c * KT;
    int tap = k >> 6, e = k & 63;
    float v = 0.f;
    if (c < HID && e < EMB) v = conv_w[(c * EMB + e) * 3 + tap];
    __nv_bfloat16 h = __float2bfloat16(v);
    __nv_bfloat16 l = __float2bfloat16(v - __bfloat162float(h));
    g_Bh[idx] = h;
    g_Bl[idx] = l;
}

// ---------------- kernel 1: persistent mma.sync encoder ---------------------
// Single 130-row A slab per precision (no tap copies); taps realized by
// shifted ldmatrix row bases. Single build + single MMA phase per sentence.
// Warp (msplit = wid>>2 in {0,1}, nsplit = wid&3): rows [64*msplit, +64)
// (4 m16 blocks) x n-tiles [8*nsplit, +8) (last split 5 real +1 pad pair).
__global__ void __launch_bounds__(256, 1) enc_kernel(
    const int* __restrict__ X, const int* __restrict__ pos1,
    const int* __restrict__ pos2,
    const float* __restrict__ word_emb, const float* __restrict__ p1e,
    const float* __restrict__ p2e, const float* __restrict__ conv_b)
{
    extern __shared__ char sm_raw[];
    const uint32_t raw  = smem_u32(sm_raw);
    const uint32_t base = (raw + 127u) & ~127u;
    float* scr = (float*)(sm_raw + (base - raw) + OFF_SCR);

    const int tid  = threadIdx.x;
    const int wid  = tid >> 5;
    const int lane = tid & 31;

    // ---- stage resident B (hi+lo), swizzled rows of 384B
    for (int t = tid; t < NPC2 * KT / 4; t += 256) {
        int idx = t * 4;
        int c = idx / KT, k = idx - c * KT;
        uint32_t off = (uint32_t)c * 384u
                     + (((uint32_t)k * 2u) ^ (((uint32_t)(c & 7)) << 4));
        sts64(base + OFF_BH + off, *reinterpret_cast<const uint2*>(g_Bh + idx));
        sts64(base + OFF_BL + off, *reinterpret_cast<const uint2*>(g_Bl + idx));
    }
    // ---- zero A slabs ONCE (pads persist; data rows overwritten per sentence)
    for (int t = tid; t < 2 * 16640 / 16; t += 256)
        sts128z(base + OFF_AH + (uint32_t)t * 16u);
    __syncthreads();

    // ---- per-warp tiling
    const int msplit = wid >> 2;            // 0/1 -> rows [64*msplit, +64)
    const int nsplit = wid & 3;
    const int nt0    = nsplit * 8;
    const int ntn    = (nsplit < 3) ? 8 : 6;    // last split: tiles 24..29 (pad 29)
    const int npair  = ntn >> 1;

    // ldmatrix lane addressing (validated pattern)
    const uint32_t lrow = (uint32_t)((lane & 7) + ((lane >> 3) & 1) * 8);
    const uint32_t lkb  = ((uint32_t)(lane >> 4) & 1u) * 16u;
    const uint32_t brow = (uint32_t)((lane & 7) + ((lane >> 4) & 1) * 8);
    const uint32_t bkb  = ((uint32_t)(lane >> 3) & 1u) * 16u;

    for (int n = blockIdx.x; n < NS; n += GRID_ENC) {
        // ================= build A (hi + lo in ONE pass) =================
        // pairs (l, e0=2*ep): 128*30 = 3840 iterations
        for (int idx = tid; idx < SL * 30; idx += 256) {
            int l = idx / 30, ep = idx - l * 30;
            int e0 = ep * 2;
            float x0, x1;
            if (e0 < VEC - 2 || e0 == VEC - 2) {         // word pairs (e0 even <50)
                int tok = X[n * SL + l];
                float2 w = *reinterpret_cast<const float2*>(word_emb + tok * VEC + e0);
                x0 = w.x; x1 = w.y;
            } else if (e0 < 54) {                        // p1 pairs (50,51),(52,53)
                int tok = pos1[n * SL + l];
                x0 = p1e[tok * PDIM + (e0 - 50)];
                x1 = p1e[tok * PDIM + (e0 - 49)];
            } else if (e0 == 54) {                       // boundary (p1[4], p2[0])
                x0 = p1e[pos1[n * SL + l] * PDIM + 4];
                x1 = p2e[pos2[n * SL + l] * PDIM + 0];
            } else {                                     // p2 pairs (56,57),(58,59)
                int tok = pos2[n * SL + l];
                x0 = p2e[tok * PDIM + (e0 - 55)];
                x1 = p2e[tok * PDIM + (e0 - 54)];
            }
            __nv_bfloat16 h0 = __float2bfloat16(x0);
            __nv_bfloat16 h1 = __float2bfloat16(x1);
            __nv_bfloat16 l0 = __float2bfloat16(x0 - __bfloat162float(h0));
            __nv_bfloat16 l1 = __float2bfloat16(x1 - __bfloat162float(h1));
            uint32_t uh = (uint32_t)__bfloat16_as_ushort(h0)
                        | ((uint32_t)__bfloat16_as_ushort(h1) << 16);
            uint32_t ul = (uint32_t)__bfloat16_as_ushort(l0)
                        | ((uint32_t)__bfloat16_as_ushort(l1) << 16);
            uint32_t p   = (uint32_t)(l + 1);
            uint32_t off = p * 128u + (((uint32_t)e0 * 2u) ^ ((p & 7u) << 4));
            sts32(base + OFF_AH + off, uh);
            sts32(base + OFF_AL + off, ul);
        }
        __syncthreads();

        // ================= MMA phase =================
        float acc[4][8][4];
        #pragma unroll
        for (int mb = 0; mb < 4; mb++)
            #pragma unroll
            for (int nt = 0; nt < 8; nt++)
                #pragma unroll
                for (int q = 0; q < 4; q++) acc[mb][nt][q] = 0.f;

        for (int t = 0; t < 3; t++) {
            #pragma unroll
            for (int ks = 0; ks < 4; ks++) {
                // B frags for this (tap, ks): pairs of n-tiles, hi and lo
                uint32_t bh[4][4], bl[4][4];
                const uint32_t kbB = (uint32_t)(t * 128 + ks * 32) + bkb;
                #pragma unroll
                for (int pp = 0; pp < 4; pp++) {
                    if (pp < npair) {
                        uint32_t c = (uint32_t)(nt0 + 2 * pp) * 8u + brow;
                        uint32_t off = c * 384u + (kbB ^ ((c & 7u) << 4));
                        ldsm4(bh[pp][0], bh[pp][1], bh[pp][2], bh[pp][3],
                              base + OFF_BH + off);
                        ldsm4(bl[pp][0], bl[pp][1], bl[pp][2], bl[pp][3],
                              base + OFF_BL + off);
                    }
                }
                const uint32_t kbA = (uint32_t)(ks * 32) + lkb;
                #pragma unroll
                for (int mb = 0; mb < 4; mb++) {
                    uint32_t r = (uint32_t)(msplit * 64 + mb * 16 + t) + lrow;
                    uint32_t aoff = r * 128u + (kbA ^ ((r & 7u) << 4));
                    uint32_t ah[4], al[4];
                    ldsm4(ah[0], ah[1], ah[2], ah[3], base + OFF_AH + aoff);
                    ldsm4(al[0], al[1], al[2], al[3], base + OFF_AL + aoff);
                    #pragma unroll
                    for (int nt = 0; nt < 8; nt++) {
                        if (nt < ntn) {
                            int pp = nt >> 1, hf = (nt & 1) * 2;
                            uint32_t b0 = bh[pp][hf], b1 = bh[pp][hf + 1];
                            uint32_t c0 = bl[pp][hf], c1 = bl[pp][hf + 1];
                            mma16816(acc[mb][nt], ah, b0, b1);   // Ah*Bh
                            mma16816(acc[mb][nt], ah, c0, c1);   // Ah*Bl
                            mma16816(acc[mb][nt], al, b0, b1);   // Al*Bh
                        }
                    }
                }
            }
        }

        // ================= epilogue: max over positions =================
        // frag: lane j holds cols 2*(j&3), +1 ; rows j>>2, (j>>2)+8
        #pragma unroll
        for (int nt = 0; nt < 8; nt++) {
            if (nt < ntn) {
                float ve = -1e30f, vo = -1e30f;
                #pragma unroll
                for (int mb = 0; mb < 4; mb++) {
                    ve = fmaxf(ve, fmaxf(acc[mb][nt][0], acc[mb][nt][2]));
                    vo = fmaxf(vo, fmaxf(acc[mb][nt][1], acc[mb][nt][3]));
                }
                #pragma unroll
                for (int o = 4; o <= 16; o <<= 1) {
                    ve = fmaxf(ve, __shfl_xor_sync(0xffffffffu, ve, o));
                    vo = fmaxf(vo, __shfl_xor_sync(0xffffffffu, vo, o));
                }
                if (lane < 4) {
                    int col = (nt0 + nt) * 8 + 2 * lane;
                    scr[msplit * NPC2 + col]     = ve;
                    scr[msplit * NPC2 + col + 1] = vo;
                }
            }
        }
        __syncthreads();
        if (tid < HID) {
            float m  = fmaxf(scr[tid], scr[NPC2 + tid]);
            float hv = m + conv_b[tid];
            g_h[n * HID + tid] = hv > 0.f ? hv : 0.f;
        }
        __syncthreads();
    }
}

// ---------------- kernel 2: bag attention + classifier ----------------
__global__ void __launch_bounds__(256) bag_kernel(
    const int* __restrict__ scope, const int* __restrict__ relation,
    const float* __restrict__ rel_w, const float* __restrict__ rel_b,
    float* __restrict__ out)
{
    __shared__ float rq[HID];
    __shared__ float rep[HID];
    __shared__ float logits[64];
    __shared__ float alpha[64];

    const int b = blockIdx.x, tid = threadIdx.x;
    const int wid = tid >> 5, lane = tid & 31;
    const int s0 = scope[2 * b], s1 = scope[2 * b + 1];
    const int sz = s1 - s0;
    const int rel = relation[b];

    for (int d = tid; d < HID; d += 256) rq[d] = rel_w[rel * HID + d];
    __syncthreads();

    for (int i = wid; i < sz && i < 64; i += 8) {
        const float* hr = g_h + (s0 + i) * HID;
        float s = 0.f;
        for (int d = lane; d < HID; d += 32) s += hr[d] * rq[d];
        #pragma unroll
        for (int o = 16; o > 0; o >>= 1) s += __shfl_xor_sync(0xffffffffu, s, o);
        if (lane == 0) logits[i] = s;
    }
    __syncthreads();

    if (tid == 0) {
        float m = -1e30f;
        for (int i = 0; i < sz && i < 64; i++) m = fmaxf(m, logits[i]);
        float den = 0.f;
        for (int i = 0; i < sz && i < 64; i++) {
            float e = expf(logits[i] - m);
            alpha[i] = e; den += e;
        }
        float inv = 1.f / den;
        for (int i = 0; i < sz && i < 64; i++) alpha[i] *= inv;
    }
    __syncthreads();

    for (int d = tid; d < HID; d += 256) {
        float a = 0.f;
        for (int i = 0; i < sz && i < 64; i++)
            a += alpha[i] * g_h[(s0 + i) * HID + d];
        rep[d] = a;
    }
    __syncthreads();

    for (int r = wid; r < NREL; r += 8) {
        float s = 0.f;
        for (int d = lane; d < HID; d += 32) s += rep[d] * rel_w[r * HID + d];
        #pragma unroll
        for (int o = 16; o > 0; o >>= 1) s += __shfl_xor_sync(0xffffffffu, s, o);
        if (lane == 0) out[b * NREL + r] = s + rel_b[r];
    }
}

// ---------------------------------------------------------------------------
extern "C" void kernel_launch(void* const* d_in, const int* in_sizes, int n_in,
                              void* d_out, int out_size)
{
    const int*   X        = (const int*)d_in[0];
    const int*   pos1     = (const int*)d_in[1];
    const int*   pos2     = (const int*)d_in[2];
    const int*   scope    = (const int*)d_in[5];
    const int*   relation = (const int*)d_in[6];
    const float* word_emb = (const float*)d_in[7];
    const float* p1e      = (const float*)d_in[8];
    const float* p2e      = (const float*)d_in[9];
    const float* conv_w   = (const float*)d_in[10];
    const float* conv_b   = (const float*)d_in[11];
    const float* rel_w    = (const float*)d_in[12];
    const float* rel_b    = (const float*)d_in[13];
    float*       out      = (float*)d_out;

    cudaFuncSetAttribute(enc_kernel,
                         cudaFuncAttributeMaxDynamicSharedMemorySize, SMEM_NEED);

    prepB<<<(NPC2 * KT + 255) / 256, 256>>>(conv_w);
    enc_kernel<<<GRID_ENC, 256, SMEM_NEED>>>(X, pos1, pos2, word_emb, p1e, p2e,
                                             conv_b);
    bag_kernel<<<NBAG, 256>>>(scope, relation, rel_w, rel_b, out);
}

// round 8
// speedup vs baseline: 3.0979x; 1.1608x over previous
#include <cuda_runtime.h>
#include <cuda_fp16.h>
#include <math.h>
#include <stdint.h>

// ---------------- problem constants ----------------
#define NS   4000
#define SL   128
#define VEC  50
#define PDIM 5
#define EMB  60
#define HID  230
#define NBAG 500
#define NREL 25

#define NPC2 240          // channels padded to 30 n-tiles (ldsm4 pairs)
#define KT   192          // K = 3 taps * 64
#define GRID_ENC 152

// smem offsets (base 128-aligned)
#define OFF_BH   0u             // 240*384 = 92160
#define OFF_BL   92160u         // 92160
#define OFF_AH   184320u        // 130 rows * 128B = 16640
#define OFF_SCR  200960u        // 2*240*4 = 1920
#define SMEM_NEED (202880 + 128)

__device__ float g_h[NS * HID];
__device__ __half g_Bh[NPC2 * KT];
__device__ __half g_Bl[NPC2 * KT];

// ---------------- helpers ----------------
__device__ __forceinline__ uint32_t smem_u32(const void* p) {
    uint32_t a;
    asm("{ .reg .u64 t; cvta.to.shared.u64 t, %1; cvt.u32.u64 %0, t; }"
        : "=r"(a) : "l"(p));
    return a;
}
__device__ __forceinline__ void sts32(uint32_t a, uint32_t v) {
    asm volatile("st.shared.u32 [%0], %1;" :: "r"(a), "r"(v));
}
__device__ __forceinline__ void sts64(uint32_t a, uint2 v) {
    asm volatile("st.shared.v2.u32 [%0], {%1,%2};" :: "r"(a), "r"(v.x), "r"(v.y));
}
__device__ __forceinline__ void sts128z(uint32_t a) {
    asm volatile("st.shared.v4.u32 [%0], {%1,%1,%1,%1};" :: "r"(a), "r"(0u));
}
__device__ __forceinline__ void ldsm4(uint32_t& r0, uint32_t& r1, uint32_t& r2,
                                      uint32_t& r3, uint32_t addr) {
    asm volatile("ldmatrix.sync.aligned.m8n8.x4.shared.b16 {%0,%1,%2,%3}, [%4];"
                 : "=r"(r0), "=r"(r1), "=r"(r2), "=r"(r3) : "r"(addr));
}
__device__ __forceinline__ void mma16816(float* c, const uint32_t* a,
                                         uint32_t b0, uint32_t b1) {
    asm volatile(
        "mma.sync.aligned.m16n8k16.row.col.f32.f16.f16.f32 "
        "{%0,%1,%2,%3}, {%4,%5,%6,%7}, {%8,%9}, {%0,%1,%2,%3};"
        : "+f"(c[0]), "+f"(c[1]), "+f"(c[2]), "+f"(c[3])
        : "r"(a[0]), "r"(a[1]), "r"(a[2]), "r"(a[3]), "r"(b0), "r"(b1));
}

// ---------------- kernel 0: conv_w -> fp16 hi/lo im2col [c][tap*64+e] -------
__global__ void prepB(const float* __restrict__ conv_w) {
    int idx = blockIdx.x * blockDim.x + threadIdx.x;
    if (idx >= NPC2 * KT) return;
    int c = idx / KT, k = idx - c * KT;
    int tap = k >> 6, e = k & 63;
    float v = 0.f;
    if (c < HID && e < EMB) v = conv_w[(c * EMB + e) * 3 + tap];
    __half h = __float2half_rn(v);
    __half l = __float2half_rn(v - __half2float(h));
    g_Bh[idx] = h;
    g_Bl[idx] = l;
}

// ---------------- kernel 1: persistent mma.sync encoder ---------------------
// fp16 2-term split: A_fp16 * (Bh + Bl). Single 130-row A slab; taps realized
// by shifted ldmatrix row bases. Warp (msplit = wid>>2, nsplit = wid&3):
// rows [64*msplit, +64) x n-tiles [8*nsplit, +8) (last split 6 tiles).
__global__ void __launch_bounds__(256, 1) enc_kernel(
    const int* __restrict__ X, const int* __restrict__ pos1,
    const int* __restrict__ pos2,
    const float* __restrict__ word_emb, const float* __restrict__ p1e,
    const float* __restrict__ p2e, const float* __restrict__ conv_b)
{
    extern __shared__ char sm_raw[];
    const uint32_t raw  = smem_u32(sm_raw);
    const uint32_t base = (raw + 127u) & ~127u;
    float* scr = (float*)(sm_raw + (base - raw) + OFF_SCR);

    const int tid  = threadIdx.x;
    const int wid  = tid >> 5;
    const int lane = tid & 31;

    // ---- stage resident B (hi+lo), swizzled rows of 384B
    for (int t = tid; t < NPC2 * KT / 4; t += 256) {
        int idx = t * 4;
        int c = idx / KT, k = idx - c * KT;
        uint32_t off = (uint32_t)c * 384u
                     + (((uint32_t)k * 2u) ^ (((uint32_t)(c & 7)) << 4));
        sts64(base + OFF_BH + off, *reinterpret_cast<const uint2*>(g_Bh + idx));
        sts64(base + OFF_BL + off, *reinterpret_cast<const uint2*>(g_Bl + idx));
    }
    // ---- zero A slab ONCE (pads persist; data rows overwritten per sentence)
    for (int t = tid; t < 16640 / 16; t += 256)
        sts128z(base + OFF_AH + (uint32_t)t * 16u);
    __syncthreads();

    // ---- per-warp tiling
    const int msplit = wid >> 2;            // 0/1 -> rows [64*msplit, +64)
    const int nsplit = wid & 3;
    const int nt0    = nsplit * 8;
    const int ntn    = (nsplit < 3) ? 8 : 6;
    const int npair  = ntn >> 1;

    // ldmatrix lane addressing
    const uint32_t lrow = (uint32_t)((lane & 7) + ((lane >> 3) & 1) * 8);
    const uint32_t lkb  = ((uint32_t)(lane >> 4) & 1u) * 16u;
    const uint32_t brow = (uint32_t)((lane & 7) + ((lane >> 4) & 1) * 8);
    const uint32_t bkb  = ((uint32_t)(lane >> 3) & 1u) * 16u;

    for (int n = blockIdx.x; n < NS; n += GRID_ENC) {
        // ================= build A (fp16, one slab) =================
        for (int idx = tid; idx < SL * 30; idx += 256) {
            int l = idx / 30, ep = idx - l * 30;
            int e0 = ep * 2;
            float x0, x1;
            if (e0 <= VEC - 2) {                         // word pairs
                int tok = X[n * SL + l];
                float2 w = *reinterpret_cast<const float2*>(word_emb + tok * VEC + e0);
                x0 = w.x; x1 = w.y;
            } else if (e0 < 54) {                        // p1 pairs
                int tok = pos1[n * SL + l];
                x0 = p1e[tok * PDIM + (e0 - 50)];
                x1 = p1e[tok * PDIM + (e0 - 49)];
            } else if (e0 == 54) {                       // boundary (p1[4], p2[0])
                x0 = p1e[pos1[n * SL + l] * PDIM + 4];
                x1 = p2e[pos2[n * SL + l] * PDIM + 0];
            } else {                                     // p2 pairs
                int tok = pos2[n * SL + l];
                x0 = p2e[tok * PDIM + (e0 - 55)];
                x1 = p2e[tok * PDIM + (e0 - 54)];
            }
            __half h0 = __float2half_rn(x0);
            __half h1 = __float2half_rn(x1);
            uint32_t uh = (uint32_t)__half_as_ushort(h0)
                        | ((uint32_t)__half_as_ushort(h1) << 16);
            uint32_t p   = (uint32_t)(l + 1);
            uint32_t off = p * 128u + (((uint32_t)e0 * 2u) ^ ((p & 7u) << 4));
            sts32(base + OFF_AH + off, uh);
        }
        __syncthreads();

        // ================= MMA phase (2 terms) =================
        float acc[4][8][4];
        #pragma unroll
        for (int mb = 0; mb < 4; mb++)
            #pragma unroll
            for (int nt = 0; nt < 8; nt++)
                #pragma unroll
                for (int q = 0; q < 4; q++) acc[mb][nt][q] = 0.f;

        for (int t = 0; t < 3; t++) {
            #pragma unroll
            for (int ks = 0; ks < 4; ks++) {
                uint32_t bh[4][4], bl[4][4];
                const uint32_t kbB = (uint32_t)(t * 128 + ks * 32) + bkb;
                #pragma unroll
                for (int pp = 0; pp < 4; pp++) {
                    if (pp < npair) {
                        uint32_t c = (uint32_t)(nt0 + 2 * pp) * 8u + brow;
                        uint32_t off = c * 384u + (kbB ^ ((c & 7u) << 4));
                        ldsm4(bh[pp][0], bh[pp][1], bh[pp][2], bh[pp][3],
                              base + OFF_BH + off);
                        ldsm4(bl[pp][0], bl[pp][1], bl[pp][2], bl[pp][3],
                              base + OFF_BL + off);
                    }
                }
                const uint32_t kbA = (uint32_t)(ks * 32) + lkb;
                #pragma unroll
                for (int mb = 0; mb < 4; mb++) {
                    uint32_t r = (uint32_t)(msplit * 64 + mb * 16 + t) + lrow;
                    uint32_t aoff = r * 128u + (kbA ^ ((r & 7u) << 4));
                    uint32_t ah[4];
                    ldsm4(ah[0], ah[1], ah[2], ah[3], base + OFF_AH + aoff);
                    #pragma unroll
                    for (int nt = 0; nt < 8; nt++) {
                        if (nt < ntn) {
                            int pp = nt >> 1, hf = (nt & 1) * 2;
                            mma16816(acc[mb][nt], ah, bh[pp][hf], bh[pp][hf + 1]);
                            mma16816(acc[mb][nt], ah, bl[pp][hf], bl[pp][hf + 1]);
                        }
                    }
                }
            }
        }

        // ================= epilogue: max over positions =================
        #pragma unroll
        for (int nt = 0; nt < 8; nt++) {
            if (nt < ntn) {
                float ve = -1e30f, vo = -1e30f;
                #pragma unroll
                for (int mb = 0; mb < 4; mb++) {
                    ve = fmaxf(ve, fmaxf(acc[mb][nt][0], acc[mb][nt][2]));
                    vo = fmaxf(vo, fmaxf(acc[mb][nt][1], acc[mb][nt][3]));
                }
                #pragma unroll
                for (int o = 4; o <= 16; o <<= 1) {
                    ve = fmaxf(ve, __shfl_xor_sync(0xffffffffu, ve, o));
                    vo = fmaxf(vo, __shfl_xor_sync(0xffffffffu, vo, o));
                }
                if (lane < 4) {
                    int col = (nt0 + nt) * 8 + 2 * lane;
                    scr[msplit * NPC2 + col]     = ve;
                    scr[msplit * NPC2 + col + 1] = vo;
                }
            }
        }
        __syncthreads();
        if (tid < HID) {
            float m  = fmaxf(scr[tid], scr[NPC2 + tid]);
            float hv = m + conv_b[tid];
            g_h[n * HID + tid] = hv > 0.f ? hv : 0.f;
        }
        __syncthreads();
    }
}

// ---------------- kernel 2: bag attention + classifier ----------------
__global__ void __launch_bounds__(256) bag_kernel(
    const int* __restrict__ scope, const int* __restrict__ relation,
    const float* __restrict__ rel_w, const float* __restrict__ rel_b,
    float* __restrict__ out)
{
    __shared__ float rq[HID];
    __shared__ float rep[HID];
    __shared__ float logits[64];
    __shared__ float alpha[64];

    const int b = blockIdx.x, tid = threadIdx.x;
    const int wid = tid >> 5, lane = tid & 31;
    const int s0 = scope[2 * b], s1 = scope[2 * b + 1];
    const int sz = s1 - s0;
    const int rel = relation[b];

    for (int d = tid; d < HID; d += 256) rq[d] = rel_w[rel * HID + d];
    __syncthreads();

    for (int i = wid; i < sz && i < 64; i += 8) {
        const float* hr = g_h + (s0 + i) * HID;
        float s = 0.f;
        for (int d = lane; d < HID; d += 32) s += hr[d] * rq[d];
        #pragma unroll
        for (int o = 16; o > 0; o >>= 1) s += __shfl_xor_sync(0xffffffffu, s, o);
        if (lane == 0) logits[i] = s;
    }
    __syncthreads();

    if (tid == 0) {
        float m = -1e30f;
        for (int i = 0; i < sz && i < 64; i++) m = fmaxf(m, logits[i]);
        float den = 0.f;
        for (int i = 0; i < sz && i < 64; i++) {
            float e = expf(logits[i] - m);
            alpha[i] = e; den += e;
        }
        float inv = 1.f / den;
        for (int i = 0; i < sz && i < 64; i++) alpha[i] *= inv;
    }
    __syncthreads();

    for (int d = tid; d < HID; d += 256) {
        float a = 0.f;
        for (int i = 0; i < sz && i < 64; i++)
            a += alpha[i] * g_h[(s0 + i) * HID + d];
        rep[d] = a;
    }
    __syncthreads();

    for (int r = wid; r < NREL; r += 8) {
        float s = 0.f;
        for (int d = lane; d < HID; d += 32) s += rep[d] * rel_w[r * HID + d];
        #pragma unroll
        for (int o = 16; o > 0; o >>= 1) s += __shfl_xor_sync(0xffffffffu, s, o);
        if (lane == 0) out[b * NREL + r] = s + rel_b[r];
    }
}

// ---------------------------------------------------------------------------
extern "C" void kernel_launch(void* const* d_in, const int* in_sizes, int n_in,
                              void* d_out, int out_size)
{
    const int*   X        = (const int*)d_in[0];
    const int*   pos1     = (const int*)d_in[1];
    const int*   pos2     = (const int*)d_in[2];
    const int*   scope    = (const int*)d_in[5];
    const int*   relation = (const int*)d_in[6];
    const float* word_emb = (const float*)d_in[7];
    const float* p1e      = (const float*)d_in[8];
    const float* p2e      = (const float*)d_in[9];
    const float* conv_w   = (const float*)d_in[10];
    const float* conv_b   = (const float*)d_in[11];
    const float* rel_w    = (const float*)d_in[12];
    const float* rel_b    = (const float*)d_in[13];
    float*       out      = (float*)d_out;

    cudaFuncSetAttribute(enc_kernel,
                         cudaFuncAttributeMaxDynamicSharedMemorySize, SMEM_NEED);

    prepB<<<(NPC2 * KT + 255) / 256, 256>>>(conv_w);
    enc_kernel<<<GRID_ENC, 256, SMEM_NEED>>>(X, pos1, pos2, word_emb, p1e, p2e,
                                             conv_b);
    bag_kernel<<<NBAG, 256>>>(scope, relation, rel_w, rel_b, out);
}